// round 10
// baseline (speedup 1.0000x reference)
#include <cuda_runtime.h>
#include <math.h>
#include <stdint.h>

#define Bq 256
#define Sq 512
#define Iq 128
#define Hq 256
#define NCTA 128
#define NTHR 512

// cluster kernel geometry
#define CPG8 8      // CTAs per cluster (portable max)
#define GB8  16     // batches per group
// fallback geometry
#define CPGF 16
#define NGRP 8
#define GBF  32

typedef unsigned long long u64;

// ---- global scratch ----
__device__ float d_enc[(size_t)Sq * Bq * Hq];   // [S][B][H]
__device__ float d_scores[Bq * Iq];             // fallback only
__device__ int   g_cnt[NGRP];                   // fallback only
__device__ int   g_phase[NGRP];                 // fallback only

// ------------------------------- helpers -----------------------------------
__device__ __forceinline__ int ld_acq(const int* p) {
    int v;
    asm volatile("ld.acquire.gpu.b32 %0, [%1];" : "=r"(v) : "l"(p) : "memory");
    return v;
}
__device__ __forceinline__ void red_release_add(int* p, int v) {
    asm volatile("red.release.gpu.global.add.s32 [%0], %1;" :: "l"(p), "r"(v) : "memory");
}
__device__ __forceinline__ void fma2(u64& d, u64 a, u64 b) {
    asm("fma.rn.f32x2 %0, %1, %2, %0;" : "+l"(d) : "l"(a), "l"(b));
}
__device__ __forceinline__ float f2sum(u64 a, float bias) {
    float lo, hi;
    asm("mov.b64 {%0,%1}, %2;" : "=f"(lo), "=f"(hi) : "l"(a));
    return lo + hi + bias;
}
__device__ __forceinline__ float fsig(float x)  { return 1.f / (1.f + __expf(-x)); }
__device__ __forceinline__ float ftanh(float x) { return 1.f - 2.f / (__expf(2.f * x) + 1.f); }

__device__ __forceinline__ uint32_t smem_u32(const void* p) {
    uint32_t a;
    asm("{ .reg .u64 t; cvta.to.shared.u64 t, %1; cvt.u32.u64 %0, t; }" : "=r"(a) : "l"(p));
    return a;
}
__device__ __forceinline__ void push_b64(uint32_t laddr, int rank, u64 v) {
    uint32_t ra;
    asm volatile("mapa.shared::cluster.u32 %0, %1, %2;" : "=r"(ra) : "r"(laddr), "r"(rank));
    asm volatile("st.shared::cluster.b64 [%0], %1;" :: "r"(ra), "l"(v) : "memory");
}
__device__ __forceinline__ void push_b32(uint32_t laddr, int rank, float v) {
    uint32_t ra;
    asm volatile("mapa.shared::cluster.u32 %0, %1, %2;" : "=r"(ra) : "r"(laddr), "r"(rank));
    asm volatile("st.shared::cluster.f32 [%0], %1;" :: "r"(ra), "f"(v) : "memory");
}
#define CLU_ARRIVE() asm volatile("barrier.cluster.arrive.aligned;" ::: "memory")
#define CLU_WAIT()   asm volatile("barrier.cluster.wait.aligned;"   ::: "memory")

// ============ CLUSTER-8 KERNEL: SMEM layout (floats) ========================
#define O_WAX   0        // 16 rows * 132  = 2112   (W_a x-part, [64|pad4|64])
#define O_WAH   2112     // 16 rows * 260  = 4160   (W_a h-part, [128|pad4|128])
#define O_WIH   6272     // 96 rows * 132  = 12672
#define O_WHH   18944    // 96 rows * 260  = 24960
#define O_BA    43904    // 16
#define O_BIH   43920    // 96
#define O_BHH   44016    // 96
#define O_HS    44112    // 128 k2 * 17 * 2 = 4352  paired h: (k,b)->((k>>1)*17+b)*2+(k&1)
#define O_XTS   48464    // 64*17*2 = 2176
#define O_XWS   50640    // 2176
#define O_GHS   52816    // 96*17 = 1632
#define O_SCS   54448    // 16*129 = 2064  scores[b][row]   (gis ALIASES this)
#define O_RED   56512    // 32
#define SMEM_FLOATS_CL 56544      // 226176 bytes

extern "C" __global__ void __launch_bounds__(NTHR)
da_rnn_cluster8(const float* __restrict__ x,
                const float* __restrict__ W_a,  const float* __restrict__ b_a,
                const float* __restrict__ W_ih, const float* __restrict__ b_ih,
                const float* __restrict__ W_hh, const float* __restrict__ b_hh,
                const float* __restrict__ W_t,  const float* __restrict__ b_t,
                const float* __restrict__ W_f,  const float* __restrict__ b_f,
                float* __restrict__ out)
{
    extern __shared__ float sm[];
    float* Wax_s = sm + O_WAX;
    float* Wah_s = sm + O_WAH;
    float* Wih_s = sm + O_WIH;
    float* Whh_s = sm + O_WHH;
    float* ba_s  = sm + O_BA;
    float* bih_s = sm + O_BIH;
    float* bhh_s = sm + O_BHH;
    float* hsf   = sm + O_HS;
    float* xtf   = sm + O_XTS;
    float* xwf   = sm + O_XWS;
    float* ghs   = sm + O_GHS;
    float* scs   = sm + O_SCS;
    float* gis   = sm + O_SCS;    // alias: scs dead after P2, gis lives P3->gates
    float* red   = sm + O_RED;
    const u64* hs64 = (const u64*)hsf;   // [k2*17 + b]
    const u64* xt64 = (const u64*)xtf;
    const u64* xw64 = (const u64*)xwf;

    const int tid   = threadIdx.x;
    const int nclus = gridDim.x >> 3;     // clusters in grid (16 / 8 / 4)
    const int ngpc  = 16 / nclus;         // batch-groups per cluster
    const int clu   = blockIdx.x >> 3;    // cluster id
    uint32_t rr_u;
    asm("mov.u32 %0, %%cluster_ctarank;" : "=r"(rr_u));
    const int rr   = (int)rr_u;           // 0..7
    const int lane = tid & 31;
    const int wrp  = tid >> 5;            // 0..15
    const int sub  = lane >> 4;           // K-half
    const int bl   = lane & 15;           // batch within half-warp
    const uint32_t smb = smem_u32(sm);

    // ---- load weight slice (once) ----
    for (int i = tid; i < 16 * 128; i += NTHR) {
        int r = i >> 7, kk = i & 127;
        Wax_s[r * 132 + kk + (kk >= 64 ? 4 : 0)] = W_a[(16 * rr + r) * 384 + kk];
    }
    for (int i = tid; i < 16 * 256; i += NTHR) {
        int r = i >> 8, kk = i & 255;
        Wah_s[r * 260 + kk + (kk >= 128 ? 4 : 0)] = W_a[(16 * rr + r) * 384 + 128 + kk];
    }
    for (int i = tid; i < 96 * 128; i += NTHR) {
        int l = i >> 7, k = i & 127;
        int grow = (l >> 5) * Hq + 32 * rr + (l & 31);
        Wih_s[l * 132 + k + (k >= 64 ? 4 : 0)] = W_ih[grow * Iq + k];
    }
    for (int i = tid; i < 96 * 256; i += NTHR) {
        int l = i >> 8, k = i & 255;
        int grow = (l >> 5) * Hq + 32 * rr + (l & 31);
        Whh_s[l * 260 + k + (k >= 128 ? 4 : 0)] = W_hh[grow * Hq + k];
    }
    if (tid < 16) ba_s[tid] = b_a[16 * rr + tid];
    if (tid < 96) {
        int grow = (tid >> 5) * Hq + 32 * rr + (tid & 31);
        bih_s[tid] = b_ih[grow];
        bhh_s[tid] = b_hh[grow];
    }

    // ================= recurrence: ngpc sequential batch-groups =================
    for (int g = 0; g < ngpc; g++) {
        const int gb0 = (clu + g * nclus) * GB8;

        for (int t = 0; t < Sq; t++) {
            // stage x_t (no h dependency; overlaps the h-wait)
            for (int i = tid; i < Iq * GB8; i += NTHR) {
                int b = i >> 7, k = i & 127;
                xtf[((k >> 1) * 17 + b) * 2 + (k & 1)] = x[((size_t)(gb0 + b) * Sq + t) * Iq + k];
            }
            if (t == 0) {
                // safe: peers cannot push h for this group's t=0 until after the
                // score barrier below, which requires our arrive (after this init)
                for (int i = tid; i < 128 * 17 * 2; i += NTHR) hsf[i] = 0.f;
            } else {
                CLU_WAIT();                       // h(t-1) pushes from all ranks landed
            }
            __syncthreads();

            // ---- P1: warp w -> score row w + gh rows 6w..6w+5; half-warps split K ----
            {
                const int w = wrp;
                const int R = 6 * w;
                u64 sacc = 0ull, a0 = 0ull, a1 = 0ull, a2 = 0ull, a3 = 0ull, a4 = 0ull, a5 = 0ull;

                const u64* wax = (const u64*)(sm + O_WAX) + w * 66 + sub * 34;
                const int kx = sub * 32;
                #pragma unroll 4
                for (int i = 0; i < 32; i += 2) {
                    u64 x0 = xt64[(kx + i) * 17 + bl];
                    u64 x1 = xt64[(kx + i + 1) * 17 + bl];
                    ulonglong2 wv = *(const ulonglong2*)(wax + i);
                    fma2(sacc, wv.x, x0); fma2(sacc, wv.y, x1);
                }
                const u64* wah = (const u64*)(sm + O_WAH) + w * 130 + sub * 66;
                const u64* wg  = (const u64*)(sm + O_WHH) + R * 130 + sub * 66;
                const int kh = sub * 64;
                #pragma unroll 4
                for (int i = 0; i < 64; i += 2) {
                    u64 h0 = hs64[(kh + i) * 17 + bl];
                    u64 h1 = hs64[(kh + i + 1) * 17 + bl];
                    ulonglong2 wv;
                    wv = *(const ulonglong2*)(wah + i);       fma2(sacc, wv.x, h0); fma2(sacc, wv.y, h1);
                    wv = *(const ulonglong2*)(wg + i);        fma2(a0, wv.x, h0);   fma2(a0, wv.y, h1);
                    wv = *(const ulonglong2*)(wg + 130 + i);  fma2(a1, wv.x, h0);   fma2(a1, wv.y, h1);
                    wv = *(const ulonglong2*)(wg + 260 + i);  fma2(a2, wv.x, h0);   fma2(a2, wv.y, h1);
                    wv = *(const ulonglong2*)(wg + 390 + i);  fma2(a3, wv.x, h0);   fma2(a3, wv.y, h1);
                    wv = *(const ulonglong2*)(wg + 520 + i);  fma2(a4, wv.x, h0);   fma2(a4, wv.y, h1);
                    wv = *(const ulonglong2*)(wg + 650 + i);  fma2(a5, wv.x, h0);   fma2(a5, wv.y, h1);
                }
                // combine K-halves (sub0 <-> sub1, same batch)
                float s  = f2sum(sacc, 0.f); s  += __shfl_xor_sync(0xffffffffu, s, 16);
                float g0 = f2sum(a0, 0.f);   g0 += __shfl_xor_sync(0xffffffffu, g0, 16);
                float g1 = f2sum(a1, 0.f);   g1 += __shfl_xor_sync(0xffffffffu, g1, 16);
                float g2 = f2sum(a2, 0.f);   g2 += __shfl_xor_sync(0xffffffffu, g2, 16);
                float g3 = f2sum(a3, 0.f);   g3 += __shfl_xor_sync(0xffffffffu, g3, 16);
                float g4 = f2sum(a4, 0.f);   g4 += __shfl_xor_sync(0xffffffffu, g4, 16);
                float g5 = f2sum(a5, 0.f);   g5 += __shfl_xor_sync(0xffffffffu, g5, 16);
                if (sub == 0) {
                    ghs[(R + 0) * 17 + bl] = g0 + bhh_s[R + 0];
                    ghs[(R + 1) * 17 + bl] = g1 + bhh_s[R + 1];
                    ghs[(R + 2) * 17 + bl] = g2 + bhh_s[R + 2];
                    ghs[(R + 3) * 17 + bl] = g3 + bhh_s[R + 3];
                    ghs[(R + 4) * 17 + bl] = g4 + bhh_s[R + 4];
                    ghs[(R + 5) * 17 + bl] = g5 + bhh_s[R + 5];
                }
                // finalize + push score (each half-warp pushes to 4 ranks)
                s = ftanh(s + ba_s[w]);
                uint32_t soff = smb + (uint32_t)((O_SCS + bl * 129 + 16 * rr + w) * 4);
                #pragma unroll
                for (int r = 0; r < 4; r++) push_b32(soff, sub * 4 + r, s);
            }
            CLU_ARRIVE();                          // release score pushes
            CLU_WAIT();                            // all 128 scores present in scs

            // ---- P2: softmax + xw. warp w <-> batch w ----
            {
                const int b2 = wrp;
                const float* sp = scs + b2 * 129;
                float e0 = __expf(sp[lane]);
                float e1 = __expf(sp[lane + 32]);
                float e2 = __expf(sp[lane + 64]);
                float e3 = __expf(sp[lane + 96]);
                float ssum = e0 + e1 + e2 + e3;
                #pragma unroll
                for (int off = 16; off; off >>= 1) ssum += __shfl_xor_sync(0xffffffffu, ssum, off);
                float inv = 1.f / ssum;
                int k = lane;
                xwf[((k >> 1) * 17 + b2) * 2 + (k & 1)] = e0 * inv * xtf[((k >> 1) * 17 + b2) * 2 + (k & 1)];
                k = lane + 32;
                xwf[((k >> 1) * 17 + b2) * 2 + (k & 1)] = e1 * inv * xtf[((k >> 1) * 17 + b2) * 2 + (k & 1)];
                k = lane + 64;
                xwf[((k >> 1) * 17 + b2) * 2 + (k & 1)] = e2 * inv * xtf[((k >> 1) * 17 + b2) * 2 + (k & 1)];
                k = lane + 96;
                xwf[((k >> 1) * 17 + b2) * 2 + (k & 1)] = e3 * inv * xtf[((k >> 1) * 17 + b2) * 2 + (k & 1)];
            }
            __syncthreads();       // xwf ready; scs reads done (gis alias write next)

            // ---- P3: gi rows 6w..6w+5, K-split halves ----
            {
                const int w = wrp;
                const int R = 6 * w;
                const u64* wi = (const u64*)(sm + O_WIH) + R * 66 + sub * 34;
                u64 c0 = 0ull, c1 = 0ull, c2 = 0ull, c3 = 0ull, c4 = 0ull, c5 = 0ull;
                const int kx = sub * 32;
                #pragma unroll 4
                for (int i = 0; i < 32; i += 2) {
                    u64 x0 = xw64[(kx + i) * 17 + bl];
                    u64 x1 = xw64[(kx + i + 1) * 17 + bl];
                    ulonglong2 wv;
                    wv = *(const ulonglong2*)(wi + i);        fma2(c0, wv.x, x0); fma2(c0, wv.y, x1);
                    wv = *(const ulonglong2*)(wi + 66 + i);   fma2(c1, wv.x, x0); fma2(c1, wv.y, x1);
                    wv = *(const ulonglong2*)(wi + 132 + i);  fma2(c2, wv.x, x0); fma2(c2, wv.y, x1);
                    wv = *(const ulonglong2*)(wi + 198 + i);  fma2(c3, wv.x, x0); fma2(c3, wv.y, x1);
                    wv = *(const ulonglong2*)(wi + 264 + i);  fma2(c4, wv.x, x0); fma2(c4, wv.y, x1);
                    wv = *(const ulonglong2*)(wi + 330 + i);  fma2(c5, wv.x, x0); fma2(c5, wv.y, x1);
                }
                float q0 = f2sum(c0, 0.f); q0 += __shfl_xor_sync(0xffffffffu, q0, 16);
                float q1 = f2sum(c1, 0.f); q1 += __shfl_xor_sync(0xffffffffu, q1, 16);
                float q2 = f2sum(c2, 0.f); q2 += __shfl_xor_sync(0xffffffffu, q2, 16);
                float q3 = f2sum(c3, 0.f); q3 += __shfl_xor_sync(0xffffffffu, q3, 16);
                float q4 = f2sum(c4, 0.f); q4 += __shfl_xor_sync(0xffffffffu, q4, 16);
                float q5 = f2sum(c5, 0.f); q5 += __shfl_xor_sync(0xffffffffu, q5, 16);
                if (sub == 0) {
                    gis[(R + 0) * 17 + bl] = q0 + bih_s[R + 0];
                    gis[(R + 1) * 17 + bl] = q1 + bih_s[R + 1];
                    gis[(R + 2) * 17 + bl] = q2 + bih_s[R + 2];
                    gis[(R + 3) * 17 + bl] = q3 + bih_s[R + 3];
                    gis[(R + 4) * 17 + bl] = q4 + bih_s[R + 4];
                    gis[(R + 5) * 17 + bl] = q5 + bih_s[R + 5];
                }
            }
            __syncthreads();

            // ---- gates + h push: (unit-pair u2, batch) per thread; halves split ranks ----
            {
                const int tt   = tid & 255;
                const int half = tid >> 8;
                const int u2   = tt & 15;        // unit pair 2u2, 2u2+1 (of own 32 units)
                const int b2   = tt >> 4;        // 0..15
                const int u0 = 2 * u2, u1 = u0 + 1;

                float r0 = fsig(gis[u0 * 17 + b2] + ghs[u0 * 17 + b2]);
                float z0 = fsig(gis[(32 + u0) * 17 + b2] + ghs[(32 + u0) * 17 + b2]);
                float n0 = ftanh(gis[(64 + u0) * 17 + b2] + r0 * ghs[(64 + u0) * 17 + b2]);
                float r1 = fsig(gis[u1 * 17 + b2] + ghs[u1 * 17 + b2]);
                float z1 = fsig(gis[(32 + u1) * 17 + b2] + ghs[(32 + u1) * 17 + b2]);
                float n1 = ftanh(gis[(64 + u1) * 17 + b2] + r1 * ghs[(64 + u1) * 17 + b2]);

                const int hidx = ((16 * rr + u2) * 17 + b2) * 2;   // own unit-pair slot
                float hp0 = hsf[hidx], hp1 = hsf[hidx + 1];
                float hn0 = (1.f - z0) * n0 + z0 * hp0;
                float hn1 = (1.f - z1) * n1 + z1 * hp1;

                __syncthreads();    // all local hsf reads done before own pushes land

                u64 pk;
                asm("mov.b64 %0, {%1,%2};" : "=l"(pk) : "f"(hn0), "f"(hn1));
                uint32_t hoff = smb + (uint32_t)((O_HS + hidx) * 4);
                #pragma unroll
                for (int r = 0; r < 4; r++) push_b64(hoff, half * 4 + r, pk);

                if (half == 0) {
                    float2 st; st.x = hn0; st.y = hn1;
                    *(float2*)&d_enc[((size_t)t * Bq + gb0 + b2) * Hq + 32 * rr + u0] = st;
                }
            }
            CLU_ARRIVE();                          // release h pushes + d_enc stores
        }
        CLU_WAIT();                                // close out last step's arrives
        __syncthreads();
    }
    __threadfence();
    __syncthreads();

    // ================= temporal attention + FC (2 batches/CTA per group) ===========
    float* wts = xtf;     // 256 floats
    float* ess = ghs;     // 512 floats
    float* prt = scs;     // 512 floats
    if (tid < Hq) wts[tid] = W_t[tid];
    const float btv = b_t[0];
    const float bfv = b_f[0];
    __syncthreads();

    for (int g = 0; g < ngpc; g++) {
        const int gb0 = (clu + g * nclus) * GB8;
        for (int bi = 0; bi < 2; bi++) {
            int bb = gb0 + 2 * rr + bi;

            for (int tt = wrp; tt < Sq; tt += 16) {
                const float* er = d_enc + ((size_t)tt * Bq + bb) * Hq;
                float s = 0.f;
                #pragma unroll
                for (int j = 0; j < 8; j++) s += er[lane + 32 * j] * wts[lane + 32 * j];
                #pragma unroll
                for (int off = 16; off; off >>= 1) s += __shfl_xor_sync(0xffffffffu, s, off);
                if (lane == 0) ess[tt] = __expf(ftanh(s + btv));
            }
            __syncthreads();

            float pp = ess[tid];
            #pragma unroll
            for (int off = 16; off; off >>= 1) pp += __shfl_xor_sync(0xffffffffu, pp, off);
            if (lane == 0) red[wrp] = pp;
            __syncthreads();
            float denom = 0.f;
            #pragma unroll
            for (int j = 0; j < 16; j++) denom += red[j];

            {
                int h = tid & 255, half = tid >> 8;
                const float* eb = d_enc + ((size_t)(half * 256) * Bq + bb) * Hq + h;
                const float* ep = ess + half * 256;
                float acc = 0.f;
                #pragma unroll 4
                for (int tt = 0; tt < 256; tt++)
                    acc += ep[tt] * eb[(size_t)tt * Bq * Hq];
                prt[tid] = acc;
            }
            __syncthreads();

            if (tid < Hq) {
                float ctx = (prt[tid] + prt[tid + 256]) / denom;
                float part = ctx * W_f[tid];
                #pragma unroll
                for (int off = 16; off; off >>= 1) part += __shfl_xor_sync(0xffffffffu, part, off);
                if (lane == 0) red[16 + wrp] = part;
            }
            __syncthreads();
            if (tid == 0) {
                float lg = bfv;
                #pragma unroll
                for (int j = 0; j < 8; j++) lg += red[16 + j];
                out[bb] = 1.f / (1.f + __expf(-lg));
            }
            __syncthreads();
        }
    }
}

// ===================== FALLBACK (proven R7/R8 kernel, L2 barriers) ==========
#define F_WA   0
#define F_WIH  3072
#define F_WHH  9216
#define F_BA   21504
#define F_BIH  21512
#define F_BHH  21560
#define F_HS   21608
#define F_XTS  30056
#define F_XWS  34280
#define F_GIS  38504
#define F_GHS  40088
#define F_RED  41672
#define SMEM_FLOATS_FB 41704

__device__ __forceinline__ void group_barrier(int g, int& want) {
    __threadfence();
    __syncthreads();
    if (threadIdx.x == 0) {
        want++;
        int old = atomicAdd(&g_cnt[g], 1);
        if (old == CPGF - 1) {
            atomicExch(&g_cnt[g], 0);
            red_release_add(&g_phase[g], 1);
        } else {
            while (ld_acq(&g_phase[g]) < want) { }
        }
    }
    __syncthreads();
    __threadfence();
}

extern "C" __global__ void __launch_bounds__(NTHR)
da_rnn_fb(const float* __restrict__ x,
          const float* __restrict__ W_a,  const float* __restrict__ b_a,
          const float* __restrict__ W_ih, const float* __restrict__ b_ih,
          const float* __restrict__ W_hh, const float* __restrict__ b_hh,
          const float* __restrict__ W_t,  const float* __restrict__ b_t,
          const float* __restrict__ W_f,  const float* __restrict__ b_f,
          float* __restrict__ out)
{
    extern __shared__ float sm[];
    float* Wa_s  = sm + F_WA;
    float* Wih_s = sm + F_WIH;
    float* Whh_s = sm + F_WHH;
    float* ba_s  = sm + F_BA;
    float* bih_s = sm + F_BIH;
    float* bhh_s = sm + F_BHH;
    float* hsf   = sm + F_HS;
    float* xtf   = sm + F_XTS;
    float* xwf   = sm + F_XWS;
    float* gis   = sm + F_GIS;
    float* ghs   = sm + F_GHS;
    float* red   = sm + F_RED;
    const u64* hs64 = (const u64*)hsf;
    const u64* xt64 = (const u64*)xtf;
    const u64* xw64 = (const u64*)xwf;

    const int tid  = threadIdx.x;
    const int grp  = blockIdx.x >> 4;
    const int rr   = blockIdx.x & 15;
    const int gb0  = grp * GBF;
    const int lane = tid & 31;
    const int wrp  = tid >> 5;

    for (int i = tid; i < 8 * 384; i += NTHR)
        Wa_s[i] = W_a[3072 * rr + i];
    for (int i = tid; i < 48 * 128; i += NTHR) {
        int l = i >> 7, k = i & 127;
        int grow = (l >> 4) * Hq + 16 * rr + (l & 15);
        Wih_s[i] = W_ih[grow * Iq + k];
    }
    for (int i = tid; i < 48 * 256; i += NTHR) {
        int l = i >> 8, k = i & 255;
        int grow = (l >> 4) * Hq + 16 * rr + (l & 15);
        Whh_s[i] = W_hh[grow * Hq + k];
    }
    if (tid < 8) ba_s[tid] = b_a[8 * rr + tid];
    if (tid < 48) {
        int grow = (tid >> 4) * Hq + 16 * rr + (tid & 15);
        bih_s[tid] = b_ih[grow];
        bhh_s[tid] = b_hh[grow];
    }

    int want = 0;
    if (tid == 0) want = ld_acq(&g_phase[grp]);
    __syncthreads();

    for (int t = 0; t < Sq; t++) {
        if (t == 0) {
            for (int i = tid; i < Hq * GBF; i += NTHR) {
                int b = i >> 8, u = i & 255;
                hsf[((u >> 1) * 33 + b) * 2 + (u & 1)] = 0.f;
            }
        } else {
            const float* ep = d_enc + (size_t)(t - 1) * Bq * Hq + (size_t)gb0 * Hq;
            for (int i = tid; i < Hq * GBF; i += NTHR) {
                int b = i >> 8, u = i & 255;
                hsf[((u >> 1) * 33 + b) * 2 + (u & 1)] = ep[b * Hq + u];
            }
        }
        for (int i = tid; i < Iq * GBF; i += NTHR) {
            int b = i >> 7, k = i & 127;
            xtf[((k >> 1) * 33 + b) * 2 + (k & 1)] = x[((size_t)(gb0 + b) * Sq + t) * Iq + k];
        }
        __syncthreads();

        if (wrp < 8) {
            const int srow = wrp;
            const int R = 2 * wrp;
            const u64* wax = (const u64*)(Wa_s + srow * 384);
            u64 sacc = 0ull;
            #pragma unroll 4
            for (int k2 = 0; k2 < 64; k2 += 2) {
                u64 x0 = xt64[k2 * 33 + lane];
                u64 x1 = xt64[(k2 + 1) * 33 + lane];
                ulonglong2 w = *(const ulonglong2*)(wax + k2);
                fma2(sacc, w.x, x0); fma2(sacc, w.y, x1);
            }
            const u64* wah = wax + 64;
            const u64* wg0 = (const u64*)(Whh_s + R * Hq);
            const u64* wg1 = wg0 + 128;
            u64 a0 = 0ull, a1 = 0ull;
            #pragma unroll 2
            for (int k2 = 0; k2 < 128; k2 += 2) {
                u64 h0 = hs64[k2 * 33 + lane];
                u64 h1 = hs64[(k2 + 1) * 33 + lane];
                ulonglong2 wa = *(const ulonglong2*)(wah + k2);
                fma2(sacc, wa.x, h0); fma2(sacc, wa.y, h1);
                ulonglong2 w0 = *(const ulonglong2*)(wg0 + k2);
                fma2(a0, w0.x, h0); fma2(a0, w0.y, h1);
                ulonglong2 w1 = *(const ulonglong2*)(wg1 + k2);
                fma2(a1, w1.x, h0); fma2(a1, w1.y, h1);
            }
            d_scores[(gb0 + lane) * Iq + 8 * rr + srow] = tanhf(f2sum(sacc, ba_s[srow]));
            ghs[R * 33 + lane]       = f2sum(a0, bhh_s[R]);
            ghs[(R + 1) * 33 + lane] = f2sum(a1, bhh_s[R + 1]);
        } else {
            const int R = 16 + 4 * (wrp - 8);
            const u64* w0 = (const u64*)(Whh_s + R * Hq);
            const u64* w1 = w0 + 128;
            const u64* w2 = w0 + 256;
            const u64* w3 = w0 + 384;
            u64 a0 = 0ull, a1 = 0ull, a2 = 0ull, a3 = 0ull;
            #pragma unroll 2
            for (int k2 = 0; k2 < 128; k2 += 2) {
                u64 h0 = hs64[k2 * 33 + lane];
                u64 h1 = hs64[(k2 + 1) * 33 + lane];
                ulonglong2 v0 = *(const ulonglong2*)(w0 + k2);
                fma2(a0, v0.x, h0); fma2(a0, v0.y, h1);
                ulonglong2 v1 = *(const ulonglong2*)(w1 + k2);
                fma2(a1, v1.x, h0); fma2(a1, v1.y, h1);
                ulonglong2 v2 = *(const ulonglong2*)(w2 + k2);
                fma2(a2, v2.x, h0); fma2(a2, v2.y, h1);
                ulonglong2 v3 = *(const ulonglong2*)(w3 + k2);
                fma2(a3, v3.x, h0); fma2(a3, v3.y, h1);
            }
            ghs[R * 33 + lane]       = f2sum(a0, bhh_s[R]);
            ghs[(R + 1) * 33 + lane] = f2sum(a1, bhh_s[R + 1]);
            ghs[(R + 2) * 33 + lane] = f2sum(a2, bhh_s[R + 2]);
            ghs[(R + 3) * 33 + lane] = f2sum(a3, bhh_s[R + 3]);
        }
        group_barrier(grp, want);

        #pragma unroll
        for (int bi = 0; bi < 2; bi++) {
            int b = 2 * wrp + bi;
            const float* sp = d_scores + (size_t)(gb0 + b) * Iq;
            float e0 = expf(sp[lane]);
            float e1 = expf(sp[lane + 32]);
            float e2 = expf(sp[lane + 64]);
            float e3 = expf(sp[lane + 96]);
            float s = e0 + e1 + e2 + e3;
            #pragma unroll
            for (int off = 16; off; off >>= 1) s += __shfl_xor_sync(0xffffffffu, s, off);
            float inv = 1.f / s;
            int k = lane;
            xwf[((k >> 1) * 33 + b) * 2 + (k & 1)] = e0 * inv * xtf[((k >> 1) * 33 + b) * 2 + (k & 1)];
            k = lane + 32;
            xwf[((k >> 1) * 33 + b) * 2 + (k & 1)] = e1 * inv * xtf[((k >> 1) * 33 + b) * 2 + (k & 1)];
            k = lane + 64;
            xwf[((k >> 1) * 33 + b) * 2 + (k & 1)] = e2 * inv * xtf[((k >> 1) * 33 + b) * 2 + (k & 1)];
            k = lane + 96;
            xwf[((k >> 1) * 33 + b) * 2 + (k & 1)] = e3 * inv * xtf[((k >> 1) * 33 + b) * 2 + (k & 1)];
        }
        __syncthreads();

        {
            const int R = 3 * wrp;
            const u64* w0 = (const u64*)(Wih_s + R * Iq);
            const u64* w1 = w0 + 64;
            const u64* w2 = w0 + 128;
            u64 a0 = 0ull, a1 = 0ull, a2 = 0ull;
            #pragma unroll 4
            for (int k2 = 0; k2 < 64; k2 += 2) {
                u64 x0 = xw64[k2 * 33 + lane];
                u64 x1 = xw64[(k2 + 1) * 33 + lane];
                ulonglong2 v0 = *(const ulonglong2*)(w0 + k2);
                fma2(a0, v0.x, x0); fma2(a0, v0.y, x1);
                ulonglong2 v1 = *(const ulonglong2*)(w1 + k2);
                fma2(a1, v1.x, x0); fma2(a1, v1.y, x1);
                ulonglong2 v2 = *(const ulonglong2*)(w2 + k2);
                fma2(a2, v2.x, x0); fma2(a2, v2.y, x1);
            }
            gis[R * 33 + lane]       = f2sum(a0, bih_s[R]);
            gis[(R + 1) * 33 + lane] = f2sum(a1, bih_s[R + 1]);
            gis[(R + 2) * 33 + lane] = f2sum(a2, bih_s[R + 2]);
        }
        __syncthreads();

        {
            int u = tid & 15;
            int b = tid >> 4;
            float r = fsig(gis[u * 33 + b] + ghs[u * 33 + b]);
            float z = fsig(gis[(16 + u) * 33 + b] + ghs[(16 + u) * 33 + b]);
            float n = tanhf(gis[(32 + u) * 33 + b] + r * ghs[(32 + u) * 33 + b]);
            int ug = 16 * rr + u;
            float hp = hsf[((ug >> 1) * 33 + b) * 2 + (ug & 1)];
            float hn = (1.f - z) * n + z * hp;
            d_enc[((size_t)t * Bq + gb0 + b) * Hq + ug] = hn;
        }
        group_barrier(grp, want);
    }

    float* wts = xtf;
    float* ess = gis;
    float* prt = ghs;
    if (tid < Hq) wts[tid] = W_t[tid];
    const float btv = b_t[0];
    const float bfv = b_f[0];
    __syncthreads();

    for (int bi = 0; bi < 2; bi++) {
        int bb = gb0 + 2 * rr + bi;
        for (int tt = wrp; tt < Sq; tt += 16) {
            const float* er = d_enc + ((size_t)tt * Bq + bb) * Hq;
            float s = 0.f;
            #pragma unroll
            for (int j = 0; j < 8; j++) s += er[lane + 32 * j] * wts[lane + 32 * j];
            #pragma unroll
            for (int off = 16; off; off >>= 1) s += __shfl_xor_sync(0xffffffffu, s, off);
            if (lane == 0) ess[tt] = expf(tanhf(s + btv));
        }
        __syncthreads();
        float pp = ess[tid];
        #pragma unroll
        for (int off = 16; off; off >>= 1) pp += __shfl_xor_sync(0xffffffffu, pp, off);
        if (lane == 0) red[wrp] = pp;
        __syncthreads();
        float denom = 0.f;
        #pragma unroll
        for (int j = 0; j < 16; j++) denom += red[j];
        {
            int h = tid & 255, half = tid >> 8;
            const float* eb = d_enc + ((size_t)(half * 256) * Bq + bb) * Hq + h;
            const float* ep = ess + half * 256;
            float acc = 0.f;
            #pragma unroll 4
            for (int tt = 0; tt < 256; tt++)
                acc += ep[tt] * eb[(size_t)tt * Bq * Hq];
            prt[tid] = acc;
        }
        __syncthreads();
        if (tid < Hq) {
            float ctx = (prt[tid] + prt[tid + 256]) / denom;
            float part = ctx * W_f[tid];
            #pragma unroll
            for (int off = 16; off; off >>= 1) part += __shfl_xor_sync(0xffffffffu, part, off);
            if (lane == 0) red[16 + wrp] = part;
        }
        __syncthreads();
        if (tid == 0) {
            float lg = bfv;
            #pragma unroll
            for (int j = 0; j < 8; j++) lg += red[16 + j];
            out[bb] = 1.f / (1.f + expf(-lg));
        }
        __syncthreads();
    }
}

// ================================ launch ====================================
extern "C" void kernel_launch(void* const* d_in, const int* in_sizes, int n_in,
                              void* d_out, int out_size)
{
    const float* x    = (const float*)d_in[0];
    const float* W_a  = (const float*)d_in[1];
    const float* b_a  = (const float*)d_in[2];
    const float* W_ih = (const float*)d_in[3];
    const float* b_ih = (const float*)d_in[4];
    const float* W_hh = (const float*)d_in[5];
    const float* b_hh = (const float*)d_in[6];
    const float* W_t  = (const float*)d_in[7];
    const float* b_t  = (const float*)d_in[8];
    const float* W_f  = (const float*)d_in[9];
    const float* b_f  = (const float*)d_in[10];
    float* out = (float*)d_out;

    const size_t smem_cl = (size_t)SMEM_FLOATS_CL * sizeof(float);   // 226176
    cudaFuncSetAttribute(da_rnn_cluster8, cudaFuncAttributeMaxDynamicSharedMemorySize,
                         (int)smem_cl);

    cudaLaunchConfig_t cfg = {};
    cfg.gridDim  = dim3(NCTA, 1, 1);
    cfg.blockDim = dim3(NTHR, 1, 1);
    cfg.dynamicSmemBytes = smem_cl;
    cfg.stream = 0;
    cudaLaunchAttribute attrs[1];
    attrs[0].id = cudaLaunchAttributeClusterDimension;
    attrs[0].val.clusterDim.x = CPG8;   // portable cluster size
    attrs[0].val.clusterDim.y = 1;
    attrs[0].val.clusterDim.z = 1;
    cfg.attrs = attrs;
    cfg.numAttrs = 1;

    int nclu = 0;
    cudaError_t qe = cudaOccupancyMaxActiveClusters(&nclu, da_rnn_cluster8, &cfg);

    int nclusters = 0;                      // adaptive: pick grid so all clusters
    if (qe == cudaSuccess) {                // are co-resident (no wave stragglers)
        if      (nclu >= 16) nclusters = 16;
        else if (nclu >= 8)  nclusters = 8;
        else if (nclu >= 4)  nclusters = 4;
    }

    if (nclusters > 0) {
        cfg.gridDim = dim3(nclusters * CPG8, 1, 1);
        cudaLaunchKernelEx(&cfg, da_rnn_cluster8, x, W_a, b_a, W_ih, b_ih, W_hh, b_hh,
                           W_t, b_t, W_f, b_f, out);
    } else {
        (void)cudaGetLastError();   // clear query error, take proven fallback
        const size_t smem_fb = (size_t)SMEM_FLOATS_FB * sizeof(float);
        cudaFuncSetAttribute(da_rnn_fb, cudaFuncAttributeMaxDynamicSharedMemorySize,
                             (int)smem_fb);
        da_rnn_fb<<<NCTA, NTHR, smem_fb>>>(x, W_a, b_a, W_ih, b_ih, W_hh, b_hh,
                                           W_t, b_t, W_f, b_f, out);
    }
}

// round 11
// speedup vs baseline: 1.7682x; 1.7682x over previous
#include <cuda_runtime.h>
#include <math.h>
#include <stdint.h>

#define Bq 256
#define Sq 512
#define Iq 128
#define Hq 256
#define CPG 16      // CTAs per group
#define NGRP 8      // groups
#define GB 32       // batches per group
#define NCTA 128
#define NTHR 512

typedef unsigned long long u64;

// ---- global scratch ----
__device__ float d_enc[(size_t)Sq * Bq * Hq];   // [S][B][H], read-once addresses in loop
__device__ float d_scores[Bq * Iq];             // reused every step -> L1-bypass access
__device__ int   g_cnt[NGRP];
__device__ int   g_phase[NGRP];

// ------------------------------- helpers -----------------------------------
__device__ __forceinline__ int ld_acq(const int* p) {
    int v;
    asm volatile("ld.acquire.gpu.b32 %0, [%1];" : "=r"(v) : "l"(p) : "memory");
    return v;
}
__device__ __forceinline__ int atom_add_release(int* p, int v) {
    int old;
    asm volatile("atom.release.gpu.global.add.s32 %0, [%1], %2;"
                 : "=r"(old) : "l"(p), "r"(v) : "memory");
    return old;
}
__device__ __forceinline__ void red_release_add(int* p, int v) {
    asm volatile("red.release.gpu.global.add.s32 [%0], %1;" :: "l"(p), "r"(v) : "memory");
}
__device__ __forceinline__ void st_relaxed(int* p, int v) {
    asm volatile("st.relaxed.gpu.global.s32 [%0], %1;" :: "l"(p), "r"(v) : "memory");
}
__device__ __forceinline__ void fma2(u64& d, u64 a, u64 b) {
    asm("fma.rn.f32x2 %0, %1, %2, %0;" : "+l"(d) : "l"(a), "l"(b));
}
__device__ __forceinline__ float f2sum(u64 a, float bias) {
    float lo, hi;
    asm("mov.b64 {%0,%1}, %2;" : "=f"(lo), "=f"(hi) : "l"(a));
    return lo + hi + bias;
}
__device__ __forceinline__ float fsig(float x)  { return 1.f / (1.f + __expf(-x)); }
__device__ __forceinline__ float ftanh(float x) { return 1.f - 2.f / (__expf(2.f * x) + 1.f); }

// Fence-free group barrier: release-atomic arrival, acquire-poll release.
// bar.sync orders intra-CTA writes before tid0's cumulative release; readers
// re-acquire via tid0's ld.acquire + bar.sync. Cross-step-reused global data
// (d_scores) is accessed L1-bypassing (__stcg/__ldcg); d_enc recurrence
// addresses are read-once per launch (L1D is flushed at launch boundaries).
__device__ __forceinline__ void group_barrier(int g, int& want) {
    __syncthreads();
    if (threadIdx.x == 0) {
        want++;
        int old = atom_add_release(&g_cnt[g], 1);
        if (old == CPG - 1) {
            st_relaxed(&g_cnt[g], 0);          // ordered before phase bump by release
            red_release_add(&g_phase[g], 1);
        } else {
            while (ld_acq(&g_phase[g]) < want) { }
        }
    }
    __syncthreads();
}

// SMEM layout offsets (floats) — identical to proven R7 kernel
#define O_WA   0        // 8*384   = 3072
#define O_WIH  3072     // 48*128  = 6144
#define O_WHH  9216     // 48*256  = 12288
#define O_BA   21504    // 8
#define O_BIH  21512    // 48
#define O_BHH  21560    // 48
#define O_HS   21608    // paired h: (k,b)->((k>>1)*33+b)*2+(k&1)   8448
#define O_XTS  30056    // 4224
#define O_XWS  34280    // 4224
#define O_GIS  38504    // 48*33 = 1584
#define O_GHS  40088    // 1584
#define O_RED  41672    // 32
#define SMEM_FLOATS 41704

extern "C" __global__ void __launch_bounds__(NTHR)
da_rnn_kernel(const float* __restrict__ x,
              const float* __restrict__ W_a,  const float* __restrict__ b_a,
              const float* __restrict__ W_ih, const float* __restrict__ b_ih,
              const float* __restrict__ W_hh, const float* __restrict__ b_hh,
              const float* __restrict__ W_t,  const float* __restrict__ b_t,
              const float* __restrict__ W_f,  const float* __restrict__ b_f,
              float* __restrict__ out)
{
    extern __shared__ float sm[];
    float* Wa_s  = sm + O_WA;
    float* Wih_s = sm + O_WIH;
    float* Whh_s = sm + O_WHH;
    float* ba_s  = sm + O_BA;
    float* bih_s = sm + O_BIH;
    float* bhh_s = sm + O_BHH;
    float* hsf   = sm + O_HS;
    float* xtf   = sm + O_XTS;
    float* xwf   = sm + O_XWS;
    float* gis   = sm + O_GIS;
    float* ghs   = sm + O_GHS;
    float* red   = sm + O_RED;
    const u64* hs64 = (const u64*)hsf;
    const u64* xt64 = (const u64*)xtf;
    const u64* xw64 = (const u64*)xwf;
    u64* xt64w = (u64*)xtf;
    u64* hs64w = (u64*)hsf;

    const int tid  = threadIdx.x;
    const int grp  = blockIdx.x >> 4;
    const int rr   = blockIdx.x & 15;
    const int gb0  = grp * GB;
    const int lane = tid & 31;
    const int wrp  = tid >> 5;

    // ---- load weight slice into SMEM (once) ----
    for (int i = tid; i < 8 * 384; i += NTHR)
        Wa_s[i] = W_a[3072 * rr + i];
    for (int i = tid; i < 48 * 128; i += NTHR) {
        int l = i >> 7, k = i & 127;
        int grow = (l >> 4) * Hq + 16 * rr + (l & 15);
        Wih_s[i] = W_ih[grow * Iq + k];
    }
    for (int i = tid; i < 48 * 256; i += NTHR) {
        int l = i >> 8, k = i & 255;
        int grow = (l >> 4) * Hq + 16 * rr + (l & 15);
        Whh_s[i] = W_hh[grow * Hq + k];
    }
    if (tid < 8) ba_s[tid] = b_a[8 * rr + tid];
    if (tid < 48) {
        int grow = (tid >> 4) * Hq + 16 * rr + (tid & 15);
        bih_s[tid] = b_ih[grow];
        bhh_s[tid] = b_hh[grow];
    }

    int want = 0;
    if (tid == 0) want = ld_acq(&g_phase[grp]);

    // ---- x pipeline: thread owns (batch pb, k-range pk..pk+7) ----
    const int pb = tid >> 4;            // 0..31
    const int pk = (tid & 15) * 8;      // 0..120
    const float* xrow = x + ((size_t)(gb0 + pb) * Sq) * Iq + pk;

    // prologue: xtf <- x(0); px <- x(1)
    {
        float4 a0 = *(const float4*)(xrow);
        float4 a1 = *(const float4*)(xrow + 4);
        const float v[8] = {a0.x, a0.y, a0.z, a0.w, a1.x, a1.y, a1.z, a1.w};
        #pragma unroll
        for (int j = 0; j < 4; j++) {
            float2 p; p.x = v[2 * j]; p.y = v[2 * j + 1];
            ((float2*)xtf)[((pk >> 1) + j) * 33 + pb] = p;
        }
    }
    float4 pxa = *(const float4*)(xrow + (size_t)Iq);
    float4 pxb = *(const float4*)(xrow + (size_t)Iq + 4);

    // ================= recurrent loop =================
    for (int t = 0; t < Sq; t++) {
        // ---- stage h(t-1) into paired SMEM (x already staged) ----
        if (t == 0) {
            for (int i = tid; i < Hq * GB; i += NTHR) {
                int b = i >> 8, u = i & 255;
                hsf[((u >> 1) * 33 + b) * 2 + (u & 1)] = 0.f;
            }
        } else {
            // thread: batch b2 = tid>>4, units u0..u0+15
            const int b2 = tid >> 4;
            const int u0 = (tid & 15) * 16;
            const float* ep = d_enc + (size_t)(t - 1) * Bq * Hq + (size_t)(gb0 + b2) * Hq + u0;
            float4 h0 = *(const float4*)(ep);
            float4 h1 = *(const float4*)(ep + 4);
            float4 h2 = *(const float4*)(ep + 8);
            float4 h3 = *(const float4*)(ep + 12);
            const float hv[16] = {h0.x,h0.y,h0.z,h0.w, h1.x,h1.y,h1.z,h1.w,
                                  h2.x,h2.y,h2.z,h2.w, h3.x,h3.y,h3.z,h3.w};
            #pragma unroll
            for (int j = 0; j < 8; j++) {
                float2 p; p.x = hv[2 * j]; p.y = hv[2 * j + 1];
                ((float2*)hsf)[((u0 >> 1) + j) * 33 + b2] = p;
            }
        }
        __syncthreads();

        // ---- P1: scores slice + gh slice ----
        if (wrp < 8) {
            const int srow = wrp;
            const int R = 2 * wrp;
            const u64* wax = (const u64*)(Wa_s + srow * 384);
            u64 sacc = 0ull;
            #pragma unroll 4
            for (int k2 = 0; k2 < 64; k2 += 2) {
                u64 x0 = xt64[k2 * 33 + lane];
                u64 x1 = xt64[(k2 + 1) * 33 + lane];
                ulonglong2 w = *(const ulonglong2*)(wax + k2);
                fma2(sacc, w.x, x0); fma2(sacc, w.y, x1);
            }
            const u64* wah = wax + 64;
            const u64* wg0 = (const u64*)(Whh_s + R * Hq);
            const u64* wg1 = wg0 + 128;
            u64 a0 = 0ull, a1 = 0ull;
            #pragma unroll 2
            for (int k2 = 0; k2 < 128; k2 += 2) {
                u64 h0 = hs64[k2 * 33 + lane];
                u64 h1 = hs64[(k2 + 1) * 33 + lane];
                ulonglong2 wa = *(const ulonglong2*)(wah + k2);
                fma2(sacc, wa.x, h0); fma2(sacc, wa.y, h1);
                ulonglong2 w0 = *(const ulonglong2*)(wg0 + k2);
                fma2(a0, w0.x, h0); fma2(a0, w0.y, h1);
                ulonglong2 w1 = *(const ulonglong2*)(wg1 + k2);
                fma2(a1, w1.x, h0); fma2(a1, w1.y, h1);
            }
            __stcg(&d_scores[(gb0 + lane) * Iq + 8 * rr + srow],
                   ftanh(f2sum(sacc, ba_s[srow])));
            ghs[R * 33 + lane]       = f2sum(a0, bhh_s[R]);
            ghs[(R + 1) * 33 + lane] = f2sum(a1, bhh_s[R + 1]);
        } else {
            const int R = 16 + 4 * (wrp - 8);
            const u64* w0 = (const u64*)(Whh_s + R * Hq);
            const u64* w1 = w0 + 128;
            const u64* w2 = w0 + 256;
            const u64* w3 = w0 + 384;
            u64 a0 = 0ull, a1 = 0ull, a2 = 0ull, a3 = 0ull;
            #pragma unroll 2
            for (int k2 = 0; k2 < 128; k2 += 2) {
                u64 h0 = hs64[k2 * 33 + lane];
                u64 h1 = hs64[(k2 + 1) * 33 + lane];
                ulonglong2 v0 = *(const ulonglong2*)(w0 + k2);
                fma2(a0, v0.x, h0); fma2(a0, v0.y, h1);
                ulonglong2 v1 = *(const ulonglong2*)(w1 + k2);
                fma2(a1, v1.x, h0); fma2(a1, v1.y, h1);
                ulonglong2 v2 = *(const ulonglong2*)(w2 + k2);
                fma2(a2, v2.x, h0); fma2(a2, v2.y, h1);
                ulonglong2 v3 = *(const ulonglong2*)(w3 + k2);
                fma2(a3, v3.x, h0); fma2(a3, v3.y, h1);
            }
            ghs[R * 33 + lane]       = f2sum(a0, bhh_s[R]);
            ghs[(R + 1) * 33 + lane] = f2sum(a1, bhh_s[R + 1]);
            ghs[(R + 2) * 33 + lane] = f2sum(a2, bhh_s[R + 2]);
            ghs[(R + 3) * 33 + lane] = f2sum(a3, bhh_s[R + 3]);
        }
        group_barrier(grp, want);   // scores visible group-wide

        // ---- P2: softmax + xw (d_scores via L1-bypass loads) ----
        #pragma unroll
        for (int bi = 0; bi < 2; bi++) {
            int b = 2 * wrp + bi;
            const float* sp = d_scores + (size_t)(gb0 + b) * Iq;
            float e0 = __expf(__ldcg(sp + lane));
            float e1 = __expf(__ldcg(sp + lane + 32));
            float e2 = __expf(__ldcg(sp + lane + 64));
            float e3 = __expf(__ldcg(sp + lane + 96));
            float s = e0 + e1 + e2 + e3;
            #pragma unroll
            for (int off = 16; off; off >>= 1) s += __shfl_xor_sync(0xffffffffu, s, off);
            float inv = 1.f / s;
            int k = lane;
            xwf[((k >> 1) * 33 + b) * 2 + (k & 1)] = e0 * inv * xtf[((k >> 1) * 33 + b) * 2 + (k & 1)];
            k = lane + 32;
            xwf[((k >> 1) * 33 + b) * 2 + (k & 1)] = e1 * inv * xtf[((k >> 1) * 33 + b) * 2 + (k & 1)];
            k = lane + 64;
            xwf[((k >> 1) * 33 + b) * 2 + (k & 1)] = e2 * inv * xtf[((k >> 1) * 33 + b) * 2 + (k & 1)];
            k = lane + 96;
            xwf[((k >> 1) * 33 + b) * 2 + (k & 1)] = e3 * inv * xtf[((k >> 1) * 33 + b) * 2 + (k & 1)];
        }
        __syncthreads();   // xw ready; all xtf(t) reads complete

        // ---- commit prefetched x(t+1) to xtf; launch prefetch of x(t+2) ----
        if (t + 1 < Sq) {
            const float v[8] = {pxa.x, pxa.y, pxa.z, pxa.w, pxb.x, pxb.y, pxb.z, pxb.w};
            #pragma unroll
            for (int j = 0; j < 4; j++) {
                float2 p; p.x = v[2 * j]; p.y = v[2 * j + 1];
                ((float2*)xtf)[((pk >> 1) + j) * 33 + pb] = p;
            }
            if (t + 2 < Sq) {
                pxa = *(const float4*)(xrow + (size_t)(t + 2) * Iq);
                pxb = *(const float4*)(xrow + (size_t)(t + 2) * Iq + 4);
            }
        }

        // ---- P3: gi slice (3 rows/warp) ----
        {
            const int R = 3 * wrp;
            const u64* w0 = (const u64*)(Wih_s + R * Iq);
            const u64* w1 = w0 + 64;
            const u64* w2 = w0 + 128;
            u64 a0 = 0ull, a1 = 0ull, a2 = 0ull;
            #pragma unroll 4
            for (int k2 = 0; k2 < 64; k2 += 2) {
                u64 x0 = xw64[k2 * 33 + lane];
                u64 x1 = xw64[(k2 + 1) * 33 + lane];
                ulonglong2 v0 = *(const ulonglong2*)(w0 + k2);
                fma2(a0, v0.x, x0); fma2(a0, v0.y, x1);
                ulonglong2 v1 = *(const ulonglong2*)(w1 + k2);
                fma2(a1, v1.x, x0); fma2(a1, v1.y, x1);
                ulonglong2 v2 = *(const ulonglong2*)(w2 + k2);
                fma2(a2, v2.x, x0); fma2(a2, v2.y, x1);
            }
            gis[R * 33 + lane]       = f2sum(a0, bih_s[R]);
            gis[(R + 1) * 33 + lane] = f2sum(a1, bih_s[R + 1]);
            gis[(R + 2) * 33 + lane] = f2sum(a2, bih_s[R + 2]);
        }
        __syncthreads();

        // ---- gates + h_new ----
        {
            int u = tid & 15;
            int b = tid >> 4;
            float r = fsig(gis[u * 33 + b] + ghs[u * 33 + b]);
            float z = fsig(gis[(16 + u) * 33 + b] + ghs[(16 + u) * 33 + b]);
            float n = ftanh(gis[(32 + u) * 33 + b] + r * ghs[(32 + u) * 33 + b]);
            int ug = 16 * rr + u;
            float hp = hsf[((ug >> 1) * 33 + b) * 2 + (ug & 1)];
            float hn = (1.f - z) * n + z * hp;
            d_enc[((size_t)t * Bq + gb0 + b) * Hq + ug] = hn;
        }
        group_barrier(grp, want);   // h(t) visible group-wide
    }

    // ================= temporal attention + FC (2 batches/CTA) =================
    float* wts = xtf;     // reuse
    float* ess = gis;     // 512 floats
    float* prt = ghs;     // 512 floats
    if (tid < Hq) wts[tid] = W_t[tid];
    const float btv = b_t[0];
    const float bfv = b_f[0];
    __syncthreads();

    for (int bi = 0; bi < 2; bi++) {
        int bb = gb0 + 2 * rr + bi;

        for (int tt = wrp; tt < Sq; tt += 16) {
            const float* er = d_enc + ((size_t)tt * Bq + bb) * Hq;
            float s = 0.f;
            #pragma unroll
            for (int j = 0; j < 8; j++) s += er[lane + 32 * j] * wts[lane + 32 * j];
            #pragma unroll
            for (int off = 16; off; off >>= 1) s += __shfl_xor_sync(0xffffffffu, s, off);
            if (lane == 0) ess[tt] = __expf(ftanh(s + btv));
        }
        __syncthreads();

        float pp = ess[tid];
        #pragma unroll
        for (int off = 16; off; off >>= 1) pp += __shfl_xor_sync(0xffffffffu, pp, off);
        if (lane == 0) red[wrp] = pp;
        __syncthreads();
        float denom = 0.f;
        #pragma unroll
        for (int j = 0; j < 16; j++) denom += red[j];

        {
            int h = tid & 255, half = tid >> 8;
            const float* eb = d_enc + ((size_t)(half * 256) * Bq + bb) * Hq + h;
            const float* ep = ess + half * 256;
            float acc = 0.f;
            #pragma unroll 4
            for (int tt = 0; tt < 256; tt++)
                acc += ep[tt] * eb[(size_t)tt * Bq * Hq];
            prt[tid] = acc;
        }
        __syncthreads();

        if (tid < Hq) {
            float ctx = (prt[tid] + prt[tid + 256]) / denom;
            float part = ctx * W_f[tid];
            #pragma unroll
            for (int off = 16; off; off >>= 1) part += __shfl_xor_sync(0xffffffffu, part, off);
            if (lane == 0) red[16 + wrp] = part;
        }
        __syncthreads();
        if (tid == 0) {
            float lg = bfv;
            #pragma unroll
            for (int j = 0; j < 8; j++) lg += red[16 + j];
            out[bb] = 1.f / (1.f + __expf(-lg));
        }
        __syncthreads();
    }
}

extern "C" void kernel_launch(void* const* d_in, const int* in_sizes, int n_in,
                              void* d_out, int out_size)
{
    const float* x    = (const float*)d_in[0];
    const float* W_a  = (const float*)d_in[1];
    const float* b_a  = (const float*)d_in[2];
    const float* W_ih = (const float*)d_in[3];
    const float* b_ih = (const float*)d_in[4];
    const float* W_hh = (const float*)d_in[5];
    const float* b_hh = (const float*)d_in[6];
    const float* W_t  = (const float*)d_in[7];
    const float* b_t  = (const float*)d_in[8];
    const float* W_f  = (const float*)d_in[9];
    const float* b_f  = (const float*)d_in[10];

    const size_t smem_bytes = (size_t)SMEM_FLOATS * sizeof(float);   // 166816
    cudaFuncSetAttribute(da_rnn_kernel, cudaFuncAttributeMaxDynamicSharedMemorySize,
                         (int)smem_bytes);
    da_rnn_kernel<<<NCTA, NTHR, smem_bytes>>>(x, W_a, b_a, W_ih, b_ih, W_hh, b_hh,
                                              W_t, b_t, W_f, b_f, (float*)d_out);
}